// round 7
// baseline (speedup 1.0000x reference)
#include <cuda_runtime.h>
#include <cuda_bf16.h>
#include <cstdint>

#define OPC 31
#define BB 64
#define DD 1024
#define NSTEP 16

// ---- GEMM tiling ----
#define KT 64            // k-tile (over d)
#define AP 72            // A smem row stride (pad: 144B = 9*16B -> conflict-free ldmatrix)
#define BPAD 136         // B smem row stride (pad: 272B = 17*16B -> conflict-free ldmatrix)
#define A_BYTES (128 * AP * 2)
#define B_BYTES (64 * BPAD * 2)
#define STAGE_BYTES (A_BYTES + 2 * B_BYTES)
#define GEMM_SMEM (2 * STAGE_BYTES)   // 106496 B, double buffered

// ---- scratch (device globals; no runtime allocation) ----
__device__ __nv_bfloat16 g_Khi[(size_t)OPC * DD * DD];   // 65 MB
__device__ __nv_bfloat16 g_Klo[(size_t)OPC * DD * DD];   // 65 MB
__device__ float         g_Y[(size_t)OPC * BB * DD];     // 8.1 MB, Y[o][b][k]
__device__ __nv_bfloat16 g_A[2 * BB * DD];               // [h_hi(64 rows); h_lo(64 rows)] x 1024
__device__ float         g_h[BB * DD];
__device__ float         g_W[NSTEP * BB * OPC];          // W[t][b][o]
__device__ float         g_gate[NSTEP * BB];             // gate[t][b]

// ---- helpers ----
static __device__ __forceinline__ uint32_t sptr(const void* p) {
    return (uint32_t)__cvta_generic_to_shared(p);
}
static __device__ __forceinline__ void cp16(void* s, const void* g) {
    asm volatile("cp.async.cg.shared.global [%0], [%1], 16;" :: "r"(sptr(s)), "l"(g));
}
static __device__ __forceinline__ void ldsm_x4(uint32_t r[4], uint32_t addr) {
    asm volatile("ldmatrix.sync.aligned.m8n8.x4.shared.b16 {%0,%1,%2,%3}, [%4];"
                 : "=r"(r[0]), "=r"(r[1]), "=r"(r[2]), "=r"(r[3]) : "r"(addr));
}
static __device__ __forceinline__ void ldsm_x4_t(uint32_t r[4], uint32_t addr) {
    asm volatile("ldmatrix.sync.aligned.m8n8.x4.trans.shared.b16 {%0,%1,%2,%3}, [%4];"
                 : "=r"(r[0]), "=r"(r[1]), "=r"(r[2]), "=r"(r[3]) : "r"(addr));
}
static __device__ __forceinline__ void mma16816(float c[4], const uint32_t a[4],
                                                uint32_t b0, uint32_t b1) {
    asm volatile("mma.sync.aligned.m16n8k16.row.col.f32.bf16.bf16.f32 "
                 "{%0,%1,%2,%3}, {%4,%5,%6,%7}, {%8,%9}, {%0,%1,%2,%3};"
                 : "+f"(c[0]), "+f"(c[1]), "+f"(c[2]), "+f"(c[3])
                 : "r"(a[0]), "r"(a[1]), "r"(a[2]), "r"(a[3]), "r"(b0), "r"(b1));
}

// ============================================================================
// 1) Split op_kernels (fp32) into bf16 hi/lo pair, same [o][d][k] layout.
// ============================================================================
__global__ void convert_kernel(const float* __restrict__ K) {
    const size_t n4 = (size_t)OPC * DD * DD / 4;
    const float4* K4 = (const float4*)K;
    uint2* Hhi = (uint2*)g_Khi;
    uint2* Hlo = (uint2*)g_Klo;
    for (size_t i = blockIdx.x * (size_t)blockDim.x + threadIdx.x; i < n4;
         i += (size_t)gridDim.x * blockDim.x) {
        float4 v = K4[i];
        float x[4] = {v.x, v.y, v.z, v.w};
        unsigned short hi[4], lo[4];
#pragma unroll
        for (int j = 0; j < 4; ++j) {
            __nv_bfloat16 h = __float2bfloat16(x[j]);
            __nv_bfloat16 l = __float2bfloat16(x[j] - __bfloat162float(h));
            hi[j] = __bfloat16_as_ushort(h);
            lo[j] = __bfloat16_as_ushort(l);
        }
        uint2 ph, pl;
        ph.x = (uint32_t)hi[0] | ((uint32_t)hi[1] << 16);
        ph.y = (uint32_t)hi[2] | ((uint32_t)hi[3] << 16);
        pl.x = (uint32_t)lo[0] | ((uint32_t)lo[1] << 16);
        pl.y = (uint32_t)lo[2] | ((uint32_t)lo[3] << 16);
        Hhi[i] = ph;
        Hlo[i] = pl;
    }
}

// ============================================================================
// 2) Softmax over opcodes + sigmoid gates for all 16 steps. One warp per (b,s).
// ============================================================================
__global__ void prep_kernel(const float* __restrict__ logits,
                            const float* __restrict__ operands) {
    int gw = (blockIdx.x * blockDim.x + threadIdx.x) >> 5;  // 0..1023
    int lane = threadIdx.x & 31;
    if (gw >= BB * NSTEP) return;
    int b = gw >> 4, s = gw & 15;
    float x = (lane < OPC) ? logits[(b * 16 + s) * OPC + lane] : -INFINITY;
    float m = x;
#pragma unroll
    for (int d = 16; d; d >>= 1) m = fmaxf(m, __shfl_xor_sync(0xffffffffu, m, d));
    float e = (lane < OPC) ? expf(x - m) : 0.f;
    float sum = e;
#pragma unroll
    for (int d = 16; d; d >>= 1) sum += __shfl_xor_sync(0xffffffffu, sum, d);
    if (lane < OPC) g_W[((size_t)s * BB + b) * OPC + lane] = e / sum;
    if (lane == 0)
        g_gate[s * BB + b] = 1.f / (1.f + expf(-operands[(b * 16 + s) * 4 + 3]));
}

// ============================================================================
// 3) h := signal; build stacked bf16 hi/lo operand A.
// ============================================================================
__global__ void init_kernel(const float* __restrict__ signal) {
    int idx = blockIdx.x * blockDim.x + threadIdx.x;
    if (idx >= BB * DD) return;
    float h = signal[idx];
    g_h[idx] = h;
    int b = idx >> 10, k = idx & 1023;
    __nv_bfloat16 hi = __float2bfloat16(h);
    g_A[idx] = hi;
    g_A[(BB + b) * DD + k] = __float2bfloat16(h - __bfloat162float(hi));
}

// ============================================================================
// 4) Per-step GEMM: grid (8 n-tiles, 31 opcodes), 384 threads (12 warps).
//    Warps 0-7:  [h_hi; h_lo](128 x d) @ K_hi  -> 128x128 tile
//    Warps 8-11:  h_hi(64 x d)         @ K_lo  ->  64x128 tile
//    Deterministic 3-phase smem reduction -> Y[o][b][n] fp32.
// ============================================================================
__device__ __forceinline__ void load_stage(char* smem_base, int s, int it, int tid,
                                           int n0, const __nv_bfloat16* Kh,
                                           const __nv_bfloat16* Kl) {
    char* base = smem_base + s * STAGE_BYTES;
    __nv_bfloat16* sA  = (__nv_bfloat16*)base;
    __nv_bfloat16* sBh = (__nv_bfloat16*)(base + A_BYTES);
    __nv_bfloat16* sBl = (__nv_bfloat16*)(base + A_BYTES + B_BYTES);
    const int d0 = it * KT;
    // A tile: 128 rows x 64 cols (16B chunks)
    for (int id = tid; id < 1024; id += 384) {
        int r = id >> 3, c = (id & 7) * 8;
        cp16(sA + r * AP + c, g_A + r * DD + d0 + c);
    }
    // B tiles: 64 rows x 128 cols, hi + lo
    for (int id = tid; id < 1024; id += 384) {
        int r = id >> 4, c = (id & 15) * 8;
        size_t goff = (size_t)(d0 + r) * DD + n0 + c;
        cp16(sBh + r * BPAD + c, Kh + goff);
        cp16(sBl + r * BPAD + c, Kl + goff);
    }
}

__global__ void __launch_bounds__(384, 1) step_gemm_kernel() {
    extern __shared__ char smem[];
    const int o  = blockIdx.y;
    const int n0 = blockIdx.x * 128;
    const int tid = threadIdx.x;
    const int w = tid >> 5, lane = tid & 31;

    const __nv_bfloat16* Kh = g_Khi + (size_t)o * DD * DD;
    const __nv_bfloat16* Kl = g_Klo + (size_t)o * DD * DD;

    const bool isP2 = (w >= 8);
    const int wl = isP2 ? (w - 8) : w;
    const int wm = (wl >> 1) * 32;   // P1: 0..96 ; P2: 0,32 (h_hi rows only)
    const int wn = (wl & 1) * 64;

    float acc[2][8][4];
#pragma unroll
    for (int i = 0; i < 2; ++i)
#pragma unroll
        for (int j = 0; j < 8; ++j)
#pragma unroll
            for (int r = 0; r < 4; ++r) acc[i][j][r] = 0.f;

    load_stage(smem, 0, 0, tid, n0, Kh, Kl);
    asm volatile("cp.async.commit_group;");

    const int lr = lane & 15;         // row-within-16 for ldmatrix addressing
    const int lc = (lane >> 4) * 8;   // 8-elem column chunk

    for (int it = 0; it < DD / KT; ++it) {
        int cur = it & 1;
        if (it + 1 < DD / KT) load_stage(smem, cur ^ 1, it + 1, tid, n0, Kh, Kl);
        asm volatile("cp.async.commit_group;");
        asm volatile("cp.async.wait_group 1;");
        __syncthreads();

        char* base = smem + cur * STAGE_BYTES;
        const __nv_bfloat16* sA = (const __nv_bfloat16*)base;
        const __nv_bfloat16* sB =
            (const __nv_bfloat16*)(base + A_BYTES + (isP2 ? B_BYTES : 0));

#pragma unroll
        for (int kb = 0; kb < KT / 16; ++kb) {
            uint32_t a[2][4];
#pragma unroll
            for (int mi = 0; mi < 2; ++mi)
                ldsm_x4(a[mi], sptr(sA + (wm + mi * 16 + lr) * AP + kb * 16 + lc));
#pragma unroll
            for (int nj = 0; nj < 4; ++nj) {
                uint32_t b[4];
                ldsm_x4_t(b, sptr(sB + (kb * 16 + lr) * BPAD + wn + nj * 16 + lc));
                mma16816(acc[0][nj * 2 + 0], a[0], b[0], b[1]);
                mma16816(acc[0][nj * 2 + 1], a[0], b[2], b[3]);
                mma16816(acc[1][nj * 2 + 0], a[1], b[0], b[1]);
                mma16816(acc[1][nj * 2 + 1], a[1], b[2], b[3]);
            }
        }
        __syncthreads();
    }

    // ---- deterministic reduction: red[64][132] overlays smem ----
    float* red = (float*)smem;
    const int rb = lane >> 2;
    const int cb = (lane & 3) * 2;

    if (!isP2 && wm < 64) {        // phase 1: h_hi @ K_hi (write)
#pragma unroll
        for (int mi = 0; mi < 2; ++mi)
#pragma unroll
            for (int nj = 0; nj < 8; ++nj)
#pragma unroll
                for (int r = 0; r < 4; ++r) {
                    int row = wm + mi * 16 + rb + ((r >> 1) << 3);
                    int col = wn + nj * 8 + cb + (r & 1);
                    red[row * 132 + col] = acc[mi][nj][r];
                }
    }
    __syncthreads();
    if (!isP2 && wm >= 64) {       // phase 2: h_lo @ K_hi (add)
#pragma unroll
        for (int mi = 0; mi < 2; ++mi)
#pragma unroll
            for (int nj = 0; nj < 8; ++nj)
#pragma unroll
                for (int r = 0; r < 4; ++r) {
                    int row = wm - 64 + mi * 16 + rb + ((r >> 1) << 3);
                    int col = wn + nj * 8 + cb + (r & 1);
                    red[row * 132 + col] += acc[mi][nj][r];
                }
    }
    __syncthreads();
    if (isP2) {                    // phase 3: h_hi @ K_lo (add)
#pragma unroll
        for (int mi = 0; mi < 2; ++mi)
#pragma unroll
            for (int nj = 0; nj < 8; ++nj)
#pragma unroll
                for (int r = 0; r < 4; ++r) {
                    int row = wm + mi * 16 + rb + ((r >> 1) << 3);
                    int col = wn + nj * 8 + cb + (r & 1);
                    red[row * 132 + col] += acc[mi][nj][r];
                }
    }
    __syncthreads();

    float* Yo = g_Y + (size_t)o * BB * DD + n0;
    for (int id = tid; id < BB * 128; id += 384) {
        int b = id >> 7, n = id & 127;
        Yo[(size_t)b * DD + n] = red[b * 132 + n];
    }
}

// ============================================================================
// 5) Per-step update: transformed = sum_o w*Y ; gate mix ; re-split h.
// ============================================================================
__global__ void step_update_kernel(int t, float* __restrict__ out, int final_step) {
    int idx = blockIdx.x * blockDim.x + threadIdx.x;
    if (idx >= BB * DD) return;
    int b = idx >> 10, k = idx & 1023;
    const float* wrow = g_W + ((size_t)t * BB + b) * OPC;
    float tr = 0.f;
#pragma unroll
    for (int o2 = 0; o2 < OPC; ++o2)
        tr = fmaf(wrow[o2], g_Y[((size_t)o2 * BB + b) * DD + k], tr);
    float g = g_gate[t * BB + b];
    float h = g_h[idx];
    float hn = g * tr + (1.f - g) * h;
    if (final_step) out[idx] = hn;
    else            g_h[idx] = hn;
    __nv_bfloat16 hi = __float2bfloat16(hn);
    g_A[idx] = hi;
    g_A[(BB + b) * DD + k] = __float2bfloat16(hn - __bfloat162float(hi));
}

// ============================================================================
// launch
// ============================================================================
extern "C" void kernel_launch(void* const* d_in, const int* in_sizes, int n_in,
                              void* d_out, int out_size) {
    const float* logits   = (const float*)d_in[0];  // (64,16,31)
    const float* operands = (const float*)d_in[1];  // (64,16,4)
    const float* signal   = (const float*)d_in[2];  // (64,1024)
    const float* opk      = (const float*)d_in[3];  // (31,1024,1024)
    float* out = (float*)d_out;                     // (64,1024)

    cudaFuncSetAttribute(step_gemm_kernel,
                         cudaFuncAttributeMaxDynamicSharedMemorySize, GEMM_SMEM);

    convert_kernel<<<4096, 256>>>(opk);
    prep_kernel<<<128, 256>>>(logits, operands);
    init_kernel<<<256, 256>>>(signal);
    for (int t = 0; t < NSTEP; ++t) {
        step_gemm_kernel<<<dim3(8, OPC), 384, GEMM_SMEM>>>();
        step_update_kernel<<<256, 256>>>(t, out, (t == NSTEP - 1) ? 1 : 0);
    }
}